// round 13
// baseline (speedup 1.0000x reference)
#include <cuda_runtime.h>
#include <cuda_fp16.h>
#include <cstdint>

// SGIntoKGPool via mma.sync m16n8k16 fp16, single GEMM (x and adj fp16-rn).
// out[b,m,c] = (sum_n adj[b,n,m] * x[b,c,n]) / max(sum_n adj[b,n,m], 1)
// B=8, C=64, N=4096, M=2048.
// Round 13: m-tile 32 -> 512 CTAs (grid was the occupancy limiter), 3 CTAs/SM,
// 10.4KB smem. A frags direct LDG from fragment-order panels, B = adj LDG ->
// fp32 degrees -> fp16 -> STS -> ldmatrix.trans. One barrier per tile.

#define BZv 8
#define Cv  64
#define Nv  4096
#define Mv  2048
#define KT  64
#define NTl (Nv / KT)       // 64 k-tiles
#define MTm 32              // m-tile

#define APANEL   8192        // A tile panel bytes (fp16 fragment order)
#define BSTRIDE  80          // bytes per B smem row (32 halfs + 16B pad)
#define BBUF     (KT * BSTRIDE)             // 5120
#define OFF_DEGS (2 * BBUF)                 // 10240
#define SMEMB    (OFF_DEGS + 128)           // 10368 (static)

// x fp16 fragment panels: per (b,kt): 16 groups (cblk*4+ks) x 32 lanes x uint4 = 8KB
__device__ uint4 g_A[BZv * NTl * 512];      // 4 MB

__device__ __forceinline__ uint32_t smem_u32(const void* p) {
    uint32_t a;
    asm("{ .reg .u64 t; cvta.to.shared.u64 t, %1; cvt.u32.u64 %0, t; }" : "=r"(a) : "l"(p));
    return a;
}
__device__ __forceinline__ void ldsm4t(uint32_t (&r)[4], uint32_t a) {
    asm volatile("ldmatrix.sync.aligned.m8n8.x4.trans.shared.b16 {%0,%1,%2,%3}, [%4];"
                 : "=r"(r[0]), "=r"(r[1]), "=r"(r[2]), "=r"(r[3]) : "r"(a));
}
__device__ __forceinline__ void mma16816(float (&d)[4], const uint4& a,
                                         uint32_t b0, uint32_t b1) {
    asm volatile("mma.sync.aligned.m16n8k16.row.col.f32.f16.f16.f32 "
                 "{%0,%1,%2,%3}, {%4,%5,%6,%7}, {%8,%9}, {%0,%1,%2,%3};"
                 : "+f"(d[0]), "+f"(d[1]), "+f"(d[2]), "+f"(d[3])
                 : "r"(a.x), "r"(a.y), "r"(a.z), "r"(a.w), "r"(b0), "r"(b1));
}
__device__ __forceinline__ unsigned packh2(float v0, float v1) {
    __half h0 = __float2half_rn(v0), h1 = __float2half_rn(v1);
    return (unsigned)__half_as_ushort(h0) | ((unsigned)__half_as_ushort(h1) << 16);
}
__device__ __forceinline__ void sts64(uint32_t a, unsigned v0, unsigned v1) {
    asm volatile("st.shared.v2.b32 [%0], {%1,%2};" :: "r"(a), "r"(v0), "r"(v1) : "memory");
}

// ---------------- prep: x -> fp16 fragment panels ----------------
// m16n8k16 A fragment: lane l holds rows {g, g+8} (g=l>>2), cols {2t,2t+1, +8} (t=l&3)
__global__ __launch_bounds__(256)
void prep_A(const float* __restrict__ x) {
    unsigned gid  = blockIdx.x * 256 + threadIdx.x;    // 262144 threads
    unsigned lid  = gid & 31;
    unsigned ks   = (gid >> 5) & 3;
    unsigned cblk = (gid >> 7) & 3;
    unsigned kt   = (gid >> 9) & (NTl - 1);
    unsigned b    = gid >> 15;

    int r0 = cblk * 16 + (lid >> 2);                   // c row
    const float* px = x + ((size_t)b * Cv + r0) * Nv + kt * KT + ks * 16 + (lid & 3) * 2;

    uint4 f;
    f.x = packh2(px[0],          px[1]);
    f.y = packh2(px[8 * Nv],     px[8 * Nv + 1]);
    f.z = packh2(px[8],          px[9]);
    f.w = packh2(px[8 * Nv + 8], px[8 * Nv + 9]);

    g_A[((size_t)(b * NTl + kt) << 9) + (cblk * 4 + ks) * 32 + lid] = f;
}

// ---------------- main kernel ----------------
__global__ __launch_bounds__(256, 3)
void sg_kg_fp16(const float* __restrict__ adj, float* __restrict__ out) {
    __shared__ __align__(16) char smem[SMEMB];
    const int tid = threadIdx.x;
    const int lid = tid & 31, wid = tid >> 5;
    const int b = blockIdx.y, m0 = blockIdx.x * MTm;
    const int cblk = wid & 3;        // c dir: 4 warps x 16 rows
    const int wc   = wid >> 2;       // m dir: 2 warps x 16 cols
    const uint32_t sb = smem_u32(smem);

    // adj lane mapping: thread owns k-row r; m float4-chunks mq and mq+4
    const int r  = tid >> 2;         // 0..63
    const int mq = tid & 3;
    const float* adjb = adj + (size_t)b * Nv * Mv + m0;

    const char* Apan = (const char*)g_A + (size_t)(b * NTl) * APANEL + lid * 16;

    float* degS = (float*)(smem + OFF_DEGS);
    if (tid < MTm) degS[tid] = 0.0f;

    float acc[2][4];
    #pragma unroll
    for (int j = 0; j < 2; j++)
        #pragma unroll
        for (int p = 0; p < 4; p++) acc[j][p] = 0.f;
    float dacc[8] = {0,0,0,0,0,0,0,0};

    // B ldsm per-thread offset (+ks*16 rows per k-step)
    const uint32_t bl = (uint32_t)((lid & 15) * BSTRIDE + (wc * 16 + (lid >> 4) * 8) * 2);
    // A fragment byte offset: group g = cblk*4 + ks, offset g*512 (+lid*16 in Apan)
    const uint32_t ag = (uint32_t)(cblk * 4) * 512;

    float4 fr0, fr1;                 // adj prefetch: row r, float4s mq and mq+4
    auto loadAdj = [&](int t) {
        const float* g = adjb + (size_t)(t * KT + r) * Mv;
        fr0 = *(const float4*)(g + mq * 4);
        fr1 = *(const float4*)(g + mq * 4 + 16);
    };
    auto stageB = [&](int bufsel) {
        dacc[0] += fr0.x; dacc[1] += fr0.y; dacc[2] += fr0.z; dacc[3] += fr0.w;
        dacc[4] += fr1.x; dacc[5] += fr1.y; dacc[6] += fr1.z; dacc[7] += fr1.w;
        uint32_t s = sb + bufsel * BBUF + r * BSTRIDE + mq * 8;
        sts64(s,      packh2(fr0.x, fr0.y), packh2(fr0.z, fr0.w));
        sts64(s + 32, packh2(fr1.x, fr1.y), packh2(fr1.z, fr1.w));
    };

    // A fragments for current tile (one uint4 per ks)
    uint4 afr[4];
    #pragma unroll
    for (int ks = 0; ks < 4; ks++)
        afr[ks] = *(const uint4*)(Apan + ag + ks * 512);

    // prologue
    loadAdj(0);
    stageB(0);
    __syncthreads();
    loadAdj(1);

    for (int t = 0; t < NTl; t++) {
        const char* Anext = Apan + (size_t)((t + 1 < NTl) ? t + 1 : t) * APANEL;
        const uint32_t sB = sb + (t & 1) * BBUF + bl;

        #pragma unroll
        for (int ks = 0; ks < 4; ks++) {
            uint32_t bb[4];
            ldsm4t(bb, sB + ks * (16 * BSTRIDE));          // k16 x m16 for this warp
            uint4 a = afr[ks];
            afr[ks] = *(const uint4*)(Anext + ag + ks * 512);   // full-tile refill slack
            mma16816(acc[0], a, bb[0], bb[1]);             // m +0..7
            mma16816(acc[1], a, bb[2], bb[3]);             // m +8..15
        }

        if (t + 1 < NTl) {
            stageB((t + 1) & 1);     // buf^1: its tile t-1 readers finished pre-barrier
            if (t + 2 < NTl) loadAdj(t + 2);
        }
        __syncthreads();             // B(t+1) visible; tile-t reads complete
    }

    // ---- degrees: exact fp32, smem atomic reduction ----
    #pragma unroll
    for (int j = 0; j < 4; j++) {
        atomicAdd(&degS[mq * 4 + j],      dacc[j]);
        atomicAdd(&degS[mq * 4 + 16 + j], dacc[4 + j]);
    }

    // ---- stage accumulators (outS aliases B buffers; disjoint from degS) ----
    float* outS = (float*)smem;      // [m][c], stride 68 floats (8704 B)
    #pragma unroll
    for (int nb = 0; nb < 2; nb++) {
        int c_row = cblk * 16 + (lid >> 2);
        int m_col = wc * 16 + nb * 8 + (lid & 3) * 2;
        outS[m_col * 68 + c_row]           = acc[nb][0];
        outS[(m_col + 1) * 68 + c_row]     = acc[nb][1];
        outS[m_col * 68 + c_row + 8]       = acc[nb][2];
        outS[(m_col + 1) * 68 + c_row + 8] = acc[nb][3];
    }
    __syncthreads();

    // ---- scaled float4 stores ----
    float* Og = out + ((size_t)b * Mv + m0) * Cv;
    #pragma unroll
    for (int i = 0; i < 2; i++) {
        int idx = tid + i * 256;                 // 512 float4s
        int ml = idx >> 4, c4 = (idx & 15) * 4;
        float4 v = *(float4*)(outS + ml * 68 + c4);
        float inv = __frcp_rn(fmaxf(degS[ml], 1.0f));
        v.x *= inv; v.y *= inv; v.z *= inv; v.w *= inv;
        *(float4*)(Og + (size_t)ml * Cv + c4) = v;
    }
}

extern "C" void kernel_launch(void* const* d_in, const int* in_sizes, int n_in,
                              void* d_out, int out_size)
{
    const float* x;
    const float* adj;
    if (in_sizes[0] == BZv * Cv * Nv) {
        x   = (const float*)d_in[0];
        adj = (const float*)d_in[1];
    } else {
        x   = (const float*)d_in[1];
        adj = (const float*)d_in[0];
    }
    float* out = (float*)d_out;

    prep_A<<<1024, 256>>>(x);                                // 262144 threads
    sg_kg_fp16<<<dim3(Mv / MTm, BZv), 256>>>(adj, out);      // 64 x 8 = 512 CTAs
}

// round 14
// speedup vs baseline: 1.8158x; 1.8158x over previous
#include <cuda_runtime.h>
#include <cuda_fp16.h>
#include <cstdint>

// SGIntoKGPool via mma.sync m16n8k16 fp16, single GEMM (x and adj fp16-rn).
// out[b,m,c] = (sum_n adj[b,n,m] * x[b,c,n]) / max(sum_n adj[b,n,m], 1)
// B=8, C=64, N=4096, M=2048.
// Round 14: R12 skeleton (MTm=64, 256 CTAs) + DOUBLE-buffered adj register
// prefetch (2 tiles / 32KB per CTA in flight; loads issued at top of the
// iteration). Registers are free: grid-limited occupancy (256/148 CTAs).

#define BZv 8
#define Cv  64
#define Nv  4096
#define Mv  2048
#define KT  64
#define NTl (Nv / KT)       // 64 k-tiles
#define MTm 64              // m-tile

#define APANEL   8192        // A tile panel bytes (fp16 fragment order)
#define BSTRIDE  144         // bytes per B smem row (64 halfs + 16B pad)
#define BBUF     (KT * BSTRIDE)             // 9216
#define OFF_DEGS (2 * BBUF)                 // 18432
#define SMEMB    (OFF_DEGS + 256)           // 18688 (static)

// x fp16 fragment panels: per (b,kt): 16 groups (cblk*4+ks) x 32 lanes x uint4 = 8KB
__device__ uint4 g_A[BZv * NTl * 512];      // 4 MB

__device__ __forceinline__ uint32_t smem_u32(const void* p) {
    uint32_t a;
    asm("{ .reg .u64 t; cvta.to.shared.u64 t, %1; cvt.u32.u64 %0, t; }" : "=r"(a) : "l"(p));
    return a;
}
__device__ __forceinline__ void ldsm4t(uint32_t (&r)[4], uint32_t a) {
    asm volatile("ldmatrix.sync.aligned.m8n8.x4.trans.shared.b16 {%0,%1,%2,%3}, [%4];"
                 : "=r"(r[0]), "=r"(r[1]), "=r"(r[2]), "=r"(r[3]) : "r"(a));
}
__device__ __forceinline__ void mma16816(float (&d)[4], const uint4& a,
                                         uint32_t b0, uint32_t b1) {
    asm volatile("mma.sync.aligned.m16n8k16.row.col.f32.f16.f16.f32 "
                 "{%0,%1,%2,%3}, {%4,%5,%6,%7}, {%8,%9}, {%0,%1,%2,%3};"
                 : "+f"(d[0]), "+f"(d[1]), "+f"(d[2]), "+f"(d[3])
                 : "r"(a.x), "r"(a.y), "r"(a.z), "r"(a.w), "r"(b0), "r"(b1));
}
__device__ __forceinline__ unsigned packh2(float v0, float v1) {
    __half h0 = __float2half_rn(v0), h1 = __float2half_rn(v1);
    return (unsigned)__half_as_ushort(h0) | ((unsigned)__half_as_ushort(h1) << 16);
}
__device__ __forceinline__ void sts128(uint32_t a, uint4 v) {
    asm volatile("st.shared.v4.b32 [%0], {%1,%2,%3,%4};"
                 :: "r"(a), "r"(v.x), "r"(v.y), "r"(v.z), "r"(v.w) : "memory");
}

// ---------------- prep: x -> fp16 fragment panels ----------------
// m16n8k16 A fragment: lane l holds rows {g, g+8} (g=l>>2), cols {2t,2t+1, +8} (t=l&3)
__global__ __launch_bounds__(256)
void prep_A(const float* __restrict__ x) {
    unsigned gid  = blockIdx.x * 256 + threadIdx.x;    // 262144 threads
    unsigned lid  = gid & 31;
    unsigned ks   = (gid >> 5) & 3;
    unsigned cblk = (gid >> 7) & 3;
    unsigned kt   = (gid >> 9) & (NTl - 1);
    unsigned b    = gid >> 15;

    int r0 = cblk * 16 + (lid >> 2);                   // c row
    const float* px = x + ((size_t)b * Cv + r0) * Nv + kt * KT + ks * 16 + (lid & 3) * 2;

    uint4 f;
    f.x = packh2(px[0],          px[1]);
    f.y = packh2(px[8 * Nv],     px[8 * Nv + 1]);
    f.z = packh2(px[8],          px[9]);
    f.w = packh2(px[8 * Nv + 8], px[8 * Nv + 9]);

    g_A[((size_t)(b * NTl + kt) << 9) + (cblk * 4 + ks) * 32 + lid] = f;
}

// ---------------- main kernel ----------------
__global__ __launch_bounds__(256, 2)
void sg_kg_fp16(const float* __restrict__ adj, float* __restrict__ out) {
    __shared__ __align__(16) char smem[SMEMB];
    const int tid = threadIdx.x;
    const int lid = tid & 31, wid = tid >> 5;
    const int b = blockIdx.y, m0 = blockIdx.x * MTm;
    const int cblk = wid & 3;        // c dir: 4 warps x 16 rows
    const int wc   = wid >> 2;       // m dir: 2 warps x 32 cols
    const uint32_t sb = smem_u32(smem);

    // adj lane mapping: thread owns k-rows r, r+32; m chunk mq*8..+7
    const int r  = tid >> 3;         // 0..31
    const int mq = tid & 7;
    const float* adjb = adj + (size_t)b * Nv * Mv + m0 + mq * 8;

    const char* Apan = (const char*)g_A + (size_t)(b * NTl) * APANEL + lid * 16;

    float* degS = (float*)(smem + OFF_DEGS);
    if (tid < MTm) degS[tid] = 0.0f;

    float acc[4][4];
    #pragma unroll
    for (int j = 0; j < 4; j++)
        #pragma unroll
        for (int p = 0; p < 4; p++) acc[j][p] = 0.f;
    float dacc[8] = {0,0,0,0,0,0,0,0};

    // B ldsm per-thread offset (+ks*16 rows per k-step)
    const uint32_t bl = (uint32_t)((lid & 15) * BSTRIDE + (wc * 32 + (lid >> 4) * 8) * 2);
    // A fragment byte offset: group g = cblk*4 + ks, offset g*512 (+lid*16 in Apan)
    const uint32_t ag = (uint32_t)(cblk * 4) * 512;

    // double-buffered adj prefetch: slot = tile & 1, 4 float4 each
    float4 fr[2][4];

    auto loadAdjS = [&](int slot, int t) {
        const float* g = adjb + (size_t)(t * KT + r) * Mv;
        fr[slot][0] = *(const float4*)(g);
        fr[slot][1] = *(const float4*)(g + 4);
        const float* g2 = g + (size_t)32 * Mv;
        fr[slot][2] = *(const float4*)(g2);
        fr[slot][3] = *(const float4*)(g2 + 4);
    };
    auto stageBS = [&](int slot, int bufsel) {
        float4 f0 = fr[slot][0], f1 = fr[slot][1];
        float4 f2 = fr[slot][2], f3 = fr[slot][3];
        dacc[0] += f0.x + f2.x; dacc[1] += f0.y + f2.y;
        dacc[2] += f0.z + f2.z; dacc[3] += f0.w + f2.w;
        dacc[4] += f1.x + f3.x; dacc[5] += f1.y + f3.y;
        dacc[6] += f1.z + f3.z; dacc[7] += f1.w + f3.w;
        uint32_t s = sb + bufsel * BBUF + r * BSTRIDE + mq * 16;
        uint4 w0 = make_uint4(packh2(f0.x, f0.y), packh2(f0.z, f0.w),
                              packh2(f1.x, f1.y), packh2(f1.z, f1.w));
        uint4 w1 = make_uint4(packh2(f2.x, f2.y), packh2(f2.z, f2.w),
                              packh2(f3.x, f3.y), packh2(f3.z, f3.w));
        sts128(s, w0);
        sts128(s + 32 * BSTRIDE, w1);
    };

    // A fragments for current tile (one uint4 per ks)
    uint4 afr[4];
    #pragma unroll
    for (int ks = 0; ks < 4; ks++)
        afr[ks] = *(const uint4*)(Apan + ag + ks * 512);

    // prologue: stage tile 0, then get tiles 1 and 2 in flight
    loadAdjS(0, 0);
    stageBS(0, 0);
    loadAdjS(1, 1);          // slot 1 <- tile 1
    loadAdjS(0, 2);          // slot 0 <- tile 2
    __syncthreads();

    #pragma unroll 2
    for (int t = 0; t < NTl; t++) {
        // stage tile t+1 into buf (t+1)&1 (its old readers finished at the
        // barrier ending iteration t-1), then refill the freed slot with t+3.
        if (t + 1 < NTl) stageBS((t + 1) & 1, (t + 1) & 1);
        if (t + 3 < NTl) loadAdjS((t + 3) & 1, t + 3);

        const char* Anext = Apan + (size_t)((t + 1 < NTl) ? t + 1 : t) * APANEL;
        const uint32_t sB = sb + (t & 1) * BBUF + bl;

        #pragma unroll
        for (int ks = 0; ks < 4; ks++) {
            uint32_t bb0[4], bb1[4];
            ldsm4t(bb0, sB + ks * (16 * BSTRIDE));         // n 0..15 of warp half
            ldsm4t(bb1, sB + ks * (16 * BSTRIDE) + 32);    // n 16..31
            uint4 a = afr[ks];
            afr[ks] = *(const uint4*)(Anext + ag + ks * 512);   // full-tile refill slack
            mma16816(acc[0], a, bb0[0], bb0[1]); mma16816(acc[1], a, bb0[2], bb0[3]);
            mma16816(acc[2], a, bb1[0], bb1[1]); mma16816(acc[3], a, bb1[2], bb1[3]);
        }

        __syncthreads();     // B(t+1) visible; tile-t buffer reads complete
    }

    // ---- degrees: exact fp32, smem atomic reduction ----
    #pragma unroll
    for (int j = 0; j < 4; j++) {
        atomicAdd(&degS[mq * 8 + j],     dacc[j]);
        atomicAdd(&degS[mq * 8 + 4 + j], dacc[4 + j]);
    }

    // ---- stage accumulators (outS aliases B buffers; disjoint from degS) ----
    float* outS = (float*)smem;      // [m][c], stride 68 floats (17408 B)
    #pragma unroll
    for (int nb = 0; nb < 4; nb++) {
        int c_row = cblk * 16 + (lid >> 2);
        int m_col = wc * 32 + nb * 8 + (lid & 3) * 2;
        outS[m_col * 68 + c_row]           = acc[nb][0];
        outS[(m_col + 1) * 68 + c_row]     = acc[nb][1];
        outS[m_col * 68 + c_row + 8]       = acc[nb][2];
        outS[(m_col + 1) * 68 + c_row + 8] = acc[nb][3];
    }
    __syncthreads();

    // ---- scaled float4 stores ----
    float* Og = out + ((size_t)b * Mv + m0) * Cv;
    #pragma unroll
    for (int i = 0; i < 4; i++) {
        int idx = tid + i * 256;                 // 1024 float4s
        int ml = idx >> 4, c4 = (idx & 15) * 4;
        float4 v = *(float4*)(outS + ml * 68 + c4);
        float inv = __frcp_rn(fmaxf(degS[ml], 1.0f));
        v.x *= inv; v.y *= inv; v.z *= inv; v.w *= inv;
        *(float4*)(Og + (size_t)ml * Cv + c4) = v;
    }
}

extern "C" void kernel_launch(void* const* d_in, const int* in_sizes, int n_in,
                              void* d_out, int out_size)
{
    const float* x;
    const float* adj;
    if (in_sizes[0] == BZv * Cv * Nv) {
        x   = (const float*)d_in[0];
        adj = (const float*)d_in[1];
    } else {
        x   = (const float*)d_in[1];
        adj = (const float*)d_in[0];
    }
    float* out = (float*)d_out;

    prep_A<<<1024, 256>>>(x);                                // 262144 threads
    sg_kg_fp16<<<dim3(Mv / MTm, BZv), 256>>>(adj, out);      // 32 x 8 = 256 CTAs
}